// round 9
// baseline (speedup 1.0000x reference)
#include <cuda_runtime.h>
#include <cuda_bf16.h>
#include <cstdint>
#include <cstddef>

// Problem constants: inputs [8192, 64], capacity = ceil(1.25*8192/64) = 160
#define S   8192
#define E   64
#define CAP 160
#define ROW (E * CAP)               // 10240 floats per token row
#define SEC ((size_t)S * ROW)       // 83,886,080 elements per [s,e,c] section

// -------- device scratch (allocation-free: __device__ globals) --------
__device__ uint8_t  g_expert[S];    // argmax expert per token
__device__ float    g_prob[S];      // softmax prob at argmax expert
__device__ unsigned g_rbits[S];     // rand[t, argmax] bits (uniform [0,1): uint order == float order)
__device__ int      g_loc[S];       // capacity slot per token, -1 if dropped

// ============================================================================
// K1: warp per token. float2 loads, fused argmax (lower-index tie-break),
// softmax denominator, prob-at-argmax = 1/sum(exp(x-max)), rand gather.
// ============================================================================
__global__ void __launch_bounds__(256) router_token_kernel(
    const float* __restrict__ inputs, const float* __restrict__ rand)
{
    int t    = blockIdx.x * 8 + (threadIdx.x >> 5);
    int lane = threadIdx.x & 31;

    float2 v = ((const float2*)(inputs + (size_t)t * E))[lane];

    float m;  int mi;
    if (v.x >= v.y) { m = v.x; mi = 2 * lane; } else { m = v.y; mi = 2 * lane + 1; }

    #pragma unroll
    for (int o = 16; o > 0; o >>= 1) {
        float om  = __shfl_xor_sync(0xFFFFFFFFu, m, o);
        int   omi = __shfl_xor_sync(0xFFFFFFFFu, mi, o);
        if (om > m || (om == m && omi < mi)) { m = om; mi = omi; }
    }

    float s = expf(v.x - m) + expf(v.y - m);
    #pragma unroll
    for (int o = 16; o > 0; o >>= 1)
        s += __shfl_xor_sync(0xFFFFFFFFu, s, o);

    if (lane == 0) {
        g_expert[t] = (uint8_t)mi;
        g_prob[t]   = 1.0f / s;
        g_rbits[t]  = __float_as_uint(rand[(size_t)t * E + mi]);
    }
}

// ============================================================================
// Block-wide inclusive scan over 1024 ints. *tot = block total.
// Safe to call repeatedly (internal syncs).
// ============================================================================
__device__ __forceinline__ int block_incl_scan_1024(int v, int* tot, int* warpsums)
{
    int lane = threadIdx.x & 31, w = threadIdx.x >> 5;
    int inc = v;
    #pragma unroll
    for (int o = 1; o < 32; o <<= 1) {
        int n = __shfl_up_sync(0xFFFFFFFFu, inc, o);
        if (lane >= o) inc += n;
    }
    if (lane == 31) warpsums[w] = inc;
    __syncthreads();
    if (w == 0) {
        int sv = warpsums[lane];
        #pragma unroll
        for (int o = 1; o < 32; o <<= 1) {
            int n = __shfl_up_sync(0xFFFFFFFFu, sv, o);
            if (lane >= o) sv += n;
        }
        warpsums[lane] = sv;
    }
    __syncthreads();
    int res = inc + (w ? warpsums[w - 1] : 0);
    *tot = warpsums[31];
    __syncthreads();
    return res;
}

// ============================================================================
// K2: one block (1024 thr) per expert. Exact radix-select for the CAP-th
// largest rand bits (common case: 1 pass since count <= CAP w.p. ~0.998),
// then ONE packed (eq|gt) block scan per chunk reproduces the cumsum slot:
// loc = gt_excl + min(eq_excl, need_eq).  Emits g_loc[] and exp_counts.
// ============================================================================
__global__ void __launch_bounds__(1024) router_select_kernel(
    float* __restrict__ out, long long counts_off)
{
    const int e   = blockIdx.x;
    const int tid = threadIdx.x;

    __shared__ unsigned hist[256];
    __shared__ int s_warpsums[32];
    __shared__ unsigned s_prefix;
    __shared__ int s_k, s_total, s_done;

    if (tid == 0) { s_prefix = 0; s_k = CAP; s_total = 0; s_done = 0; }

    for (int pass = 3; pass >= 0; --pass) {
        __syncthreads();
        if (s_done) break;
        if (tid < 256) hist[tid] = 0;
        __syncthreads();

        unsigned prefix = s_prefix;
        unsigned himask = (pass == 3) ? 0u : (0xFFFFFFFFu << ((pass + 1) * 8));
        int shift = pass * 8;

        #pragma unroll
        for (int c = 0; c < S / 1024; ++c) {
            int t = c * 1024 + tid;
            if (g_expert[t] == (uint8_t)e) {
                unsigned b = g_rbits[t];
                if ((b & himask) == (prefix & himask))
                    atomicAdd(&hist[(b >> shift) & 255u], 1u);
            }
        }
        __syncthreads();

        // suffix-sum: thread tid handles bin i = 255 - tid
        int hv = (tid < 256) ? (int)hist[255 - tid] : 0;
        int tot;
        int suf = block_incl_scan_1024(hv, &tot, s_warpsums);

        int k = s_k;   // stable: no writer since last sync
        __syncthreads();

        if (tid < 256) {
            int i = 255 - tid;
            int above = suf - hv;                  // strictly greater than bin i
            if (pass == 3 && tid == 255) {
                s_total = suf;
                if (suf <= CAP) s_done = 1;        // keep everything
            }
            if (suf >= k && above < k) {           // unique selected bin
                s_k = k - above;
                s_prefix = prefix | ((unsigned)i << shift);
            }
        }
    }
    __syncthreads();

    const int keep_all = (s_total <= CAP);
    const unsigned T   = s_prefix;
    const int need_eq  = keep_all ? 0 : s_k;
    const int total    = s_total;

    int runEq = 0, runGt = 0;
    #pragma unroll
    for (int c = 0; c < S / 1024; ++c) {
        int t = c * 1024 + tid;
        bool assigned = (g_expert[t] == (uint8_t)e);
        unsigned b = assigned ? g_rbits[t] : 0u;
        int gtf, eqf;
        if (keep_all) { gtf = assigned ? 1 : 0; eqf = 0; }
        else {
            gtf = (assigned && b >  T) ? 1 : 0;
            eqf = (assigned && b == T) ? 1 : 0;
        }
        int packed = eqf | (gtf << 16);

        int tot;
        int incl = block_incl_scan_1024(packed, &tot, s_warpsums);
        int excl = incl - packed;
        int eq_excl = runEq + (excl & 0xFFFF);
        int gt_excl = runGt + (excl >> 16);

        if (assigned) {
            int kept = gtf || (eqf && eq_excl < need_eq);
            int loc  = gt_excl + min(eq_excl, need_eq);
            g_loc[t] = kept ? loc : -1;
        }
        runEq += tot & 0xFFFF;
        runGt += tot >> 16;
    }

    if (tid == 0 && counts_off >= 0)
        out[(size_t)counts_off + e] = (float)total;
}

// ============================================================================
// K3: fix-up. One thread per token: scatter the <=8192 nonzeros into the
// pre-zeroed combine_weights / sec_mask sections.
// ============================================================================
__global__ void __launch_bounds__(256) router_fix_kernel(
    float* __restrict__ out, int write_mask)
{
    int t = blockIdx.x * 256 + threadIdx.x;
    int loc = g_loc[t];
    if (loc >= 0) {
        size_t off = (size_t)t * ROW + (size_t)g_expert[t] * CAP + loc;
        out[off] = g_prob[t];
        if (write_mask) out[SEC + off] = 1.0f;
    }
}

// ============================================================================
// Launch: event-fork the capture into two parallel graph branches.
//   Branch A (main/legacy stream): K1 token -> K2 select      (~11 us)
//   Branch B (side stream):        memset of [0, 2*SEC)       (~89 us)
//   Join -> K3 fix-up                                         (~1.5 us)
// K1/K2 touch only scratch + the counts word at 2*SEC (disjoint from the
// memset range), so the branches are race-free.
// ============================================================================
extern "C" void kernel_launch(void* const* d_in, const int* in_sizes, int n_in,
                              void* d_out, int out_size)
{
    const float* inputs = (const float*)d_in[0];  // [8192, 64] f32
    const float* rand   = (const float*)d_in[1];  // [8192, 64] f32
    float* out = (float*)d_out;
    size_t osz = (size_t)out_size;

    // Layout: out = combine_weights [s,e,c] | sec_mask [s,e,c] | exp_counts [e]
    int write_mask = (osz >= 2 * SEC) ? 1 : 0;
    long long counts_off = -1;
    if (osz > SEC && (osz % SEC) == (size_t)E) counts_off = (long long)(osz - E);

    size_t zero_elems = write_mask ? 2 * SEC : SEC;   // bulk zero region
    if (zero_elems > osz) zero_elems = osz;

    // Bytes past (bulk + counts) — zero serially up-front (normally none).
    size_t counts_elems = (counts_off >= 0) ? (size_t)E : 0;
    if (osz > zero_elems + counts_elems)
        cudaMemsetAsync((char*)d_out + (zero_elems + counts_elems) * sizeof(float), 0,
                        (osz - zero_elems - counts_elems) * sizeof(float), 0);

    // Try the forked (parallel-branch) schedule.
    cudaStream_t s1 = 0;
    cudaEvent_t evFork = 0, evJoin = 0;
    bool forked = false;
    if (cudaStreamCreateWithFlags(&s1, cudaStreamNonBlocking) == cudaSuccess) {
        if (cudaEventCreateWithFlags(&evFork, cudaEventDisableTiming) == cudaSuccess &&
            cudaEventCreateWithFlags(&evJoin, cudaEventDisableTiming) == cudaSuccess)
            forked = true;
    }

    if (forked) {
        // Fork: side stream joins the capture via the fork event.
        cudaEventRecord(evFork, 0);
        cudaStreamWaitEvent(s1, evFork, 0);

        // Branch B: bulk zero (the dominant, dependency-free work).
        cudaMemsetAsync(d_out, 0, zero_elems * sizeof(float), s1);

        // Branch A: token + select (scratch + counts word only).
        router_token_kernel<<<S / 8, 256>>>(inputs, rand);
        router_select_kernel<<<E, 1024>>>(out, counts_off);

        // Join: fix-up must see both the zero field and g_loc.
        cudaEventRecord(evJoin, s1);
        cudaStreamWaitEvent(0, evJoin, 0);
        router_fix_kernel<<<S / 256, 256>>>(out, write_mask);
        // Note: streams/events are intentionally not destroyed here —
        // destroying a stream participating in capture would invalidate the
        // capture. kernel_launch is invoked O(1) times; host-side leak is nil.
    } else {
        // Serial fallback.
        cudaMemsetAsync(d_out, 0, zero_elems * sizeof(float), 0);
        router_token_kernel<<<S / 8, 256>>>(inputs, rand);
        router_select_kernel<<<E, 1024>>>(out, counts_off);
        router_fix_kernel<<<S / 256, 256>>>(out, write_mask);
    }
}